// round 7
// baseline (speedup 1.0000x reference)
#include <cuda_runtime.h>

#define DEGREE   6
#define WIDTH    7          // DEGREE - START_DEGREE + 1
#define FEAT     1024       // in_features
#define OUTF     1024       // out_features
#define THREADS  256
#define NWARPS   8
#define ROWS_PER_BLOCK 4    // 2 warps per row, 16 features per lane

// ---- packed f32x2 helpers on float2 (sm_103a; ptxas pairs the registers) ----
__device__ __forceinline__ float2 mul2(float2 a, float2 b) {
    float2 d;
    asm("{\n\t.reg .b64 ra, rb, rd;\n\t"
        "mov.b64 ra, {%2, %3};\n\tmov.b64 rb, {%4, %5};\n\t"
        "mul.rn.f32x2 rd, ra, rb;\n\tmov.b64 {%0, %1}, rd;\n\t}"
        : "=f"(d.x), "=f"(d.y)
        : "f"(a.x), "f"(a.y), "f"(b.x), "f"(b.y));
    return d;
}
__device__ __forceinline__ float2 add2(float2 a, float2 b) {
    float2 d;
    asm("{\n\t.reg .b64 ra, rb, rd;\n\t"
        "mov.b64 ra, {%2, %3};\n\tmov.b64 rb, {%4, %5};\n\t"
        "add.rn.f32x2 rd, ra, rb;\n\tmov.b64 {%0, %1}, rd;\n\t}"
        : "=f"(d.x), "=f"(d.y)
        : "f"(a.x), "f"(a.y), "f"(b.x), "f"(b.y));
    return d;
}
__device__ __forceinline__ float2 fma2(float2 a, float2 b, float2 c) {
    float2 d;
    asm("{\n\t.reg .b64 ra, rb, rc, rd;\n\t"
        "mov.b64 ra, {%2, %3};\n\tmov.b64 rb, {%4, %5};\n\tmov.b64 rc, {%6, %7};\n\t"
        "fma.rn.f32x2 rd, ra, rb, rc;\n\tmov.b64 {%0, %1}, rd;\n\t}"
        : "=f"(d.x), "=f"(d.y)
        : "f"(a.x), "f"(a.y), "f"(b.x), "f"(b.y), "f"(c.x), "f"(c.y));
    return d;
}
__device__ __forceinline__ float ex2f(float x) {
    float r; asm("ex2.approx.f32 %0, %1;" : "=f"(r) : "f"(x)); return r;
}
__device__ __forceinline__ float clipf(float v) {
    return fminf(fmaxf(v, -100.0f), 100.0f);
}

__global__ __launch_bounds__(THREADS, 4)   // force regs <= 64 -> 32 warps/SM
void hermite_fused_kernel(const float* __restrict__ x,
                          const float* __restrict__ coeffs,
                          const float* __restrict__ sigma,
                          float* __restrict__ out)
{
    __shared__ float s_part[NWARPS][WIDTH];

    const int tid  = threadIdx.x;
    const int lane = tid & 31;
    const int warp = tid >> 5;

    const float s     = fminf(fmaxf(sigma[0], 0.1f), 5.0f);
    const float inv_s = 1.0f / s;

    // only two packed constants live through phase 1 (4 regs total):
    //   txs = x * (2/s)                (= 2*xs, all the recursion needs)
    //   ea  = x^2 * (-log2(e)/s^2)     (then g = ex2(ea) = exp(-xs^2))
    const float  two_inv_s = 2.0f * inv_s;
    const float  kexp      = -1.4426950408889634f * inv_s * inv_s;
    const float2 tis2 = { two_inv_s, two_inv_s };
    const float2 k2   = { kexp, kexp };

    // ---- Phase 1: half a row per warp (16 features/lane, front-batched) ----
    const int row  = blockIdx.x * ROWS_PER_BLOCK + (warp >> 1);
    const int half = warp & 1;
    const float4* xr = reinterpret_cast<const float4*>(x + (size_t)row * FEAT)
                       + half * (FEAT / 8);   // 128 float4 per half

    float4 xv[4];
#pragma unroll
    for (int i = 0; i < 4; ++i) xv[i] = xr[lane + 32 * i];

    float2 acc[WIDTH];
#pragma unroll
    for (int w = 0; w < WIDTH; ++w) acc[w] = make_float2(0.0f, 0.0f);

#pragma unroll
    for (int i = 0; i < 4; ++i) {
        float2 xp[2] = { make_float2(xv[i].x, xv[i].y),
                         make_float2(xv[i].z, xv[i].w) };
#pragma unroll
        for (int p = 0; p < 2; ++p) {
            const float2 txs = mul2(xp[p], tis2);        // 2*xs
            const float2 x2  = mul2(xp[p], xp[p]);
            const float2 ea  = mul2(x2, k2);             // -log2e * xs^2
            // min(xs^2,50) never binds here; delta ~e-50 << 1e-3 tolerance
            const float2 g   = make_float2(ex2f(ea.x), ex2f(ea.y));

            acc[0] = add2(acc[0], g);                    // g * H0
            acc[1] = fma2(g, txs, acc[1]);               // g * H1 (= g*2xs)

            float2 hm2 = make_float2(1.0f, 1.0f);
            float2 hm1 = txs;
#pragma unroll
            for (int n = 2; n <= DEGREE; ++n) {
                const float cn = -2.0f * (float)(n - 1); // immediate: 0 regs
                float2 t;
                t.x = hm2.x * cn;                        // FMUL-imm, rt 1
                t.y = hm2.y * cn;
                float2 h = fma2(txs, hm1, t);            // 2xs*hm1 - 2(n-1)*hm2
                h.x = clipf(h.x);                        // clip BEFORE recursion
                h.y = clipf(h.y);
                acc[n] = fma2(g, h, acc[n]);
                hm2 = hm1;
                hm1 = h;
            }
        }
    }

    // collapse packed halves -> scalar accumulators
    float a[WIDTH];
#pragma unroll
    for (int w = 0; w < WIDTH; ++w) a[w] = acc[w].x + acc[w].y;

    // ---- coeff loads (phase 2); latency hides behind reduce + barrier ----
    float4 c[7];
    {
        const float4* c4 =
            reinterpret_cast<const float4*>(coeffs + (size_t)(tid * 4) * WIDTH);
#pragma unroll
        for (int i = 0; i < 7; ++i) c[i] = c4[i];
    }

    // ---- warp-local reduction of the 7 accumulators ----
#pragma unroll
    for (int w = 0; w < WIDTH; ++w) {
#pragma unroll
        for (int off = 16; off > 0; off >>= 1)
            a[w] += __shfl_xor_sync(0xffffffffu, a[w], off);
    }
    if (lane == 0) {
#pragma unroll
        for (int w = 0; w < WIDTH; ++w)
            s_part[warp][w] = a[w];
    }

    __syncthreads();   // the ONLY barrier

    // ---- Phase 2: 4 rows x 4 outputs per thread from register coeffs ----
    const float* cf = reinterpret_cast<const float*>(c);

#pragma unroll
    for (int r = 0; r < ROWS_PER_BLOCK; ++r) {
        float bs[WIDTH];
#pragma unroll
        for (int w = 0; w < WIDTH; ++w)
            bs[w] = s_part[2 * r][w] + s_part[2 * r + 1][w];  // merge halves

        float4 o;
        float* op = reinterpret_cast<float*>(&o);
#pragma unroll
        for (int i = 0; i < 4; ++i) {
            float v = 0.0f;
#pragma unroll
            for (int w = 0; w < WIDTH; ++w)
                v += bs[w] * cf[i * WIDTH + w];
            op[i] = v;
        }
        const int orow = blockIdx.x * ROWS_PER_BLOCK + r;
        reinterpret_cast<float4*>(out + (size_t)orow * OUTF)[tid] = o;
    }
}

extern "C" void kernel_launch(void* const* d_in, const int* in_sizes, int n_in,
                              void* d_out, int out_size)
{
    const float* x      = (const float*)d_in[0];   // (4096, 1024)
    const float* coeffs = (const float*)d_in[1];   // (1024, 7)
    const float* sigma  = (const float*)d_in[2];   // (1,)
    float* out          = (float*)d_out;           // (4096, 1024)

    const int batch  = in_sizes[0] / FEAT;         // 4096
    const int nblock = batch / ROWS_PER_BLOCK;     // 1024

    hermite_fused_kernel<<<nblock, THREADS>>>(x, coeffs, sigma, out);
}